// round 6
// baseline (speedup 1.0000x reference)
#include <cuda_runtime.h>
#include <cuda_fp16.h>
#include <cstdint>

#define B_ANCH 2048
#define P_POS  4
#define D_DIM  256            // K
#define NNEG   32768
#define ALPHA  0.1f
#define EPSN   1e-12f
#define INV_T  20.0f          // 1/temperature; bound on neg_sim (cos<=1)

#define MT     128            // anchors per CTA
#define NB     64             // negatives per subtile
#define MBLKS  (B_ANCH / MT)  // 16
#define NGRP   18             // N-groups -> grid 16*18 = 288 CTAs
#define STR    272            // smem row stride bytes (256 data + 16 pad)

#define A_BYTES (MT * STR)          // 34816
#define B_BYTES (NB * STR)          // 17408
#define SMEM_TOTAL (A_BYTES + 3 * B_BYTES)   // 87040

// logit = dot * 20/127^2 ; accumulate exp(logit - 20)
#define DOT_SC (20.0f / 16129.0f)

// ---- scratch ----
__device__ uint8_t g_a8[B_ANCH * D_DIM];      // s8 (x127)
__device__ uint8_t g_n8[NNEG * D_DIM];        // s8 (x127)
__device__ float g_pos[B_ANCH * P_POS];
__device__ float g_part[NGRP * B_ANCH];       // transposed: [gp][anchor]
__device__ float g_bsum[16];

// ================= helpers =================
__device__ __forceinline__ uint32_t smem_u32(const void* p) {
    uint32_t a;
    asm("{ .reg .u64 t; cvta.to.shared.u64 t, %1; cvt.u32.u64 %0, t; }" : "=r"(a) : "l"(p));
    return a;
}
__device__ __forceinline__ void cp_async16(uint32_t dst, const void* src) {
    asm volatile("cp.async.cg.shared.global [%0], [%1], 16;" :: "r"(dst), "l"(src) : "memory");
}
#define CP_COMMIT() asm volatile("cp.async.commit_group;" ::: "memory")
#define CP_WAIT(n)  asm volatile("cp.async.wait_group %0;" :: "n"(n) : "memory")

__device__ __forceinline__ uint32_t pack_s8_4(float x, float y, float z, float w) {
    int q0 = __float2int_rn(x), q1 = __float2int_rn(y);
    int q2 = __float2int_rn(z), q3 = __float2int_rn(w);
    return (uint32_t)(q0 & 255) | ((uint32_t)(q1 & 255) << 8)
         | ((uint32_t)(q2 & 255) << 16) | ((uint32_t)(q3 & 255) << 24);
}

// int8 IMMA, s32 accumulators: c[0..1]=row g cols(2q,2q+1), c[2..3]=row g+8
__device__ __forceinline__ void mma_s8(int* c, const uint32_t* a,
                                       uint32_t b0, uint32_t b1) {
    asm volatile(
        "mma.sync.aligned.m16n8k32.row.col.s32.s8.s8.s32 "
        "{%0,%1,%2,%3}, {%4,%5,%6,%7}, {%8,%9}, {%0,%1,%2,%3};\n"
        : "+r"(c[0]), "+r"(c[1]), "+r"(c[2]), "+r"(c[3])
        : "r"(a[0]), "r"(a[1]), "r"(a[2]), "r"(a[3]), "r"(b0), "r"(b1));
}

// ============================================================
// Kernel 1: L2-normalize anchors + negatives -> s8 (x127)
// ============================================================
__global__ void normalize_kernel(const float* __restrict__ anch,
                                 const float* __restrict__ neg) {
    int warp = threadIdx.x >> 5, lane = threadIdx.x & 31;
    int row = blockIdx.x * 8 + warp;
    const float* src;
    uint8_t* dst;
    if (row < B_ANCH) {
        src = anch + (size_t)row * D_DIM;  dst = g_a8 + (size_t)row * D_DIM;
    } else {
        int r = row - B_ANCH;
        if (r >= NNEG) return;
        src = neg + (size_t)r * D_DIM;     dst = g_n8 + (size_t)r * D_DIM;
    }
    const float4* s4 = (const float4*)src;
    float4 v0 = s4[lane], v1 = s4[lane + 32];
    float ss = v0.x*v0.x + v0.y*v0.y + v0.z*v0.z + v0.w*v0.w
             + v1.x*v1.x + v1.y*v1.y + v1.z*v1.z + v1.w*v1.w;
    #pragma unroll
    for (int o = 16; o; o >>= 1) ss += __shfl_xor_sync(0xFFFFFFFFu, ss, o);
    float inv = 127.0f / fmaxf(sqrtf(ss), EPSN);
    uint32_t* d32 = (uint32_t*)dst;
    d32[lane]      = pack_s8_4(v0.x*inv, v0.y*inv, v0.z*inv, v0.w*inv);
    d32[lane + 32] = pack_s8_4(v1.x*inv, v1.y*inv, v1.z*inv, v1.w*inv);
}

// ============================================================
// Kernel 2: pos_sim in fp32 (warp per pair) — exact
// ============================================================
__global__ void pos_kernel(const float* __restrict__ anch,
                           const float* __restrict__ pos) {
    int warp = threadIdx.x >> 5, lane = threadIdx.x & 31;
    int id = blockIdx.x * 8 + warp;
    if (id >= B_ANCH * P_POS) return;
    int b = id >> 2;
    const float4* a4 = (const float4*)(anch + (size_t)b * D_DIM);
    const float4* p4 = (const float4*)(pos  + (size_t)id * D_DIM);
    float4 a0 = a4[lane], a1 = a4[lane + 32];
    float4 p0 = p4[lane], p1 = p4[lane + 32];
    float dot = a0.x*p0.x + a0.y*p0.y + a0.z*p0.z + a0.w*p0.w
              + a1.x*p1.x + a1.y*p1.y + a1.z*p1.z + a1.w*p1.w;
    float asq = a0.x*a0.x + a0.y*a0.y + a0.z*a0.z + a0.w*a0.w
              + a1.x*a1.x + a1.y*a1.y + a1.z*a1.z + a1.w*a1.w;
    float psq = p0.x*p0.x + p0.y*p0.y + p0.z*p0.z + p0.w*p0.w
              + p1.x*p1.x + p1.y*p1.y + p1.z*p1.z + p1.w*p1.w;
    #pragma unroll
    for (int o = 16; o; o >>= 1) {
        dot += __shfl_xor_sync(0xFFFFFFFFu, dot, o);
        asq += __shfl_xor_sync(0xFFFFFFFFu, asq, o);
        psq += __shfl_xor_sync(0xFFFFFFFFu, psq, o);
    }
    if (lane == 0) {
        float denom = fmaxf(sqrtf(asq), EPSN) * fmaxf(sqrtf(psq), EPSN);
        g_pos[id] = dot / denom * INV_T;
    }
}

// ============================================================
// Kernel 3: int8 IMMA GEMM + fused sum(exp(logit - 20))
// 256 threads / 8 warps; warp w owns rows 16w..16w+15.
// A fragments register-resident; B triple-buffered via cp.async.
// ============================================================
extern __shared__ uint8_t smem_raw[];

__global__ void __launch_bounds__(256, 2) gemm_lse_kernel() {
    uint8_t* sA = smem_raw;
    uint32_t sA_u = smem_u32(smem_raw);
    int tid = threadIdx.x;
    int w = tid >> 5, lane = tid & 31, g = lane >> 2, q = lane & 3;
    int m  = blockIdx.x & 15;
    int gp = blockIdx.x >> 4;
    int m0 = m * MT;
    int tstart = gp * 28 + min(gp, 8);      // 512 = 8*29 + 10*28
    int tcnt   = 28 + (gp < 8 ? 1 : 0);

    // ---- issue A tile load (32KB) ----
    {
        const uint8_t* gA = g_a8 + (size_t)m0 * D_DIM;
        #pragma unroll
        for (int i = 0; i < 8; i++) {
            int c = tid + i * 256;
            int r = c >> 4, c16 = c & 15;
            cp_async16(sA_u + r * STR + c16 * 16, gA + (size_t)r * 256 + c16 * 16);
        }
    }
    CP_COMMIT();

    // ---- preload B tiles 0,1 ----
    #pragma unroll
    for (int pb = 0; pb < 2; pb++) {
        const uint8_t* gB = g_n8 + (size_t)(tstart + pb) * NB * D_DIM;
        uint32_t sB_u = sA_u + A_BYTES + pb * B_BYTES;
        #pragma unroll
        for (int i = 0; i < 4; i++) {
            int c = tid + i * 256;
            int r = c >> 4, c16 = c & 15;
            cp_async16(sB_u + r * STR + c16 * 16, gB + (size_t)r * 256 + c16 * 16);
        }
        CP_COMMIT();
    }

    // ---- A fragments -> registers ----
    CP_WAIT(2);
    __syncthreads();
    uint32_t areg[32];
    {
        const uint8_t* r0 = sA + (size_t)(w * 16 + g) * STR;
        const uint8_t* r1 = r0 + 8 * STR;
        #pragma unroll
        for (int ks = 0; ks < 8; ks++) {
            int k0 = ks * 32;
            areg[4*ks+0] = *(const uint32_t*)(r0 + k0 + 4*q);
            areg[4*ks+1] = *(const uint32_t*)(r1 + k0 + 4*q);
            areg[4*ks+2] = *(const uint32_t*)(r0 + k0 + 16 + 4*q);
            areg[4*ks+3] = *(const uint32_t*)(r1 + k0 + 16 + 4*q);
        }
    }

    float rs0 = 0.0f, rs1 = 0.0f;

    for (int t = 0; t < tcnt; t++) {
        if (t < tcnt - 1) CP_WAIT(1); else CP_WAIT(0);
        __syncthreads();

        // prefetch tile t+2 into buffer (t+2)%3
        if (t + 2 < tcnt) {
            const uint8_t* gB = g_n8 + (size_t)(tstart + t + 2) * NB * D_DIM;
            uint32_t sB_u = sA_u + A_BYTES + ((t + 2) % 3) * B_BYTES;
            #pragma unroll
            for (int i = 0; i < 4; i++) {
                int c = tid + i * 256;
                int r = c >> 4, c16 = c & 15;
                cp_async16(sB_u + r * STR + c16 * 16, gB + (size_t)r * 256 + c16 * 16);
            }
            CP_COMMIT();
        }

        const uint8_t* sB = sA + A_BYTES + (t % 3) * B_BYTES;
        int acc[8][4];
        #pragma unroll
        for (int j = 0; j < 8; j++) {
            acc[j][0] = 0; acc[j][1] = 0; acc[j][2] = 0; acc[j][3] = 0;
        }

        #pragma unroll
        for (int ks = 0; ks < 8; ks++) {
            int k0 = ks * 32;
            #pragma unroll
            for (int j = 0; j < 8; j++) {
                const uint8_t* br = sB + (size_t)(j * 8 + g) * STR + k0 + 4*q;
                uint32_t b0 = *(const uint32_t*)(br);
                uint32_t b1 = *(const uint32_t*)(br + 16);
                mma_s8(acc[j], areg + 4*ks, b0, b1);
            }
        }

        // epilogue: logit = dot*20/127^2; accumulate exp(logit - 20)
        #pragma unroll
        for (int j = 0; j < 8; j++) {
            rs0 += __expf(fmaf(__int2float_rn(acc[j][0]), DOT_SC, -20.0f))
                 + __expf(fmaf(__int2float_rn(acc[j][1]), DOT_SC, -20.0f));
            rs1 += __expf(fmaf(__int2float_rn(acc[j][2]), DOT_SC, -20.0f))
                 + __expf(fmaf(__int2float_rn(acc[j][3]), DOT_SC, -20.0f));
        }
    }

    // reduce across the quad (cols), write per-row partials (transposed)
    rs0 += __shfl_xor_sync(0xFFFFFFFFu, rs0, 1);
    rs0 += __shfl_xor_sync(0xFFFFFFFFu, rs0, 2);
    rs1 += __shfl_xor_sync(0xFFFFFFFFu, rs1, 1);
    rs1 += __shfl_xor_sync(0xFFFFFFFFu, rs1, 2);
    if (q == 0) {
        int row = m0 + w * 16 + g;
        g_part[(size_t)gp * B_ANCH + row]     = rs0;
        g_part[(size_t)gp * B_ANCH + row + 8] = rs1;
    }
}

// ============================================================
// Kernel 4a: per-anchor loss + block partial sums (grid 16 x 128)
// ============================================================
__global__ void finalize_a_kernel(const int* __restrict__ counts) {
    __shared__ float red[128];
    int tid = threadIdx.x;
    int b = blockIdx.x * 128 + tid;

    float s = 0.0f;
    #pragma unroll
    for (int c = 0; c < NGRP; c++) s += g_part[(size_t)c * B_ANCH + b];
    float lse = 20.0f + logf(s);
    int cnt = counts[b];
    float ps[4];
    #pragma unroll
    for (int j = 0; j < 4; j++) ps[j] = g_pos[b * 4 + j];

    float local = 0.0f;
    #pragma unroll
    for (int j = 0; j < 4; j++) {
        if (j < cnt) {
            float mx = fmaxf(ps[j], lse);
            local += mx + log1pf(expf(fminf(ps[j], lse) - mx)) - ps[j];
        }
    }
    float mx = fmaxf(fmaxf(ps[0], ps[1]), fmaxf(ps[2], ps[3]));
    float e0 = expf(ps[0] - mx), e1 = expf(ps[1] - mx);
    float e2 = expf(ps[2] - mx), e3 = expf(ps[3] - mx);
    float wps = (e0*ps[0] + e1*ps[1] + e2*ps[2] + e3*ps[3]) / (e0 + e1 + e2 + e3);
    if (cnt > 1) {
        float m2 = fmaxf(wps, lse);
        local += ALPHA * (m2 + log1pf(expf(fminf(wps, lse) - m2)) - wps);
    }

    red[tid] = local;
    __syncthreads();
    #pragma unroll
    for (int o = 64; o; o >>= 1) {
        if (tid < o) red[tid] += red[tid + o];
        __syncthreads();
    }
    if (tid == 0) g_bsum[blockIdx.x] = red[0];
}

__global__ void finalize_b_kernel(float* __restrict__ out) {
    if (threadIdx.x == 0) {
        float t = 0.0f;
        #pragma unroll
        for (int i = 0; i < 16; i++) t += g_bsum[i];
        out[0] = t / (float)B_ANCH;
    }
}

// ============================================================
extern "C" void kernel_launch(void* const* d_in, const int* in_sizes, int n_in,
                              void* d_out, int out_size) {
    const float* anch   = (const float*)d_in[0];
    const float* pos    = (const float*)d_in[1];
    const float* neg    = (const float*)d_in[2];
    const int*   counts = (const int*)d_in[3];
    float* out = (float*)d_out;

    cudaFuncSetAttribute(gemm_lse_kernel,
                         cudaFuncAttributeMaxDynamicSharedMemorySize, SMEM_TOTAL);

    normalize_kernel<<<(B_ANCH + NNEG) / 8, 256>>>(anch, neg);
    pos_kernel<<<(B_ANCH * P_POS) / 8, 256>>>(anch, pos);
    gemm_lse_kernel<<<MBLKS * NGRP, 256, SMEM_TOTAL>>>();
    finalize_a_kernel<<<16, 128>>>(counts);
    finalize_b_kernel<<<1, 32>>>(out);
}

// round 8
// speedup vs baseline: 2.3235x; 2.3235x over previous
#include <cuda_runtime.h>
#include <cuda_fp16.h>
#include <cstdint>

#define B_ANCH 2048
#define P_POS  4
#define D_DIM  256            // K
#define NNEG   32768
#define ALPHA  0.1f
#define EPSN   1e-12f
#define INV_T  20.0f          // 1/temperature; bound on neg_sim (cos<=1)
#define K2E    28.85390081777927f   // 20 * log2(e)

#define MT     128            // anchors per CTA
#define NB     64             // negatives per subtile
#define MBLKS  (B_ANCH / MT)  // 16
#define NGRP   18             // N-groups -> grid 16*18 = 288 CTAs
#define STR    272            // smem row stride bytes (256 data + 16 pad)

#define A_BYTES (MT * STR)          // 34816
#define B_BYTES (NB * STR)          // 17408
#define SMEM_TOTAL (A_BYTES + 3 * B_BYTES)   // 87040

// ---- scratch ----
__device__ uint8_t g_a8[B_ANCH * D_DIM];      // e4m3
__device__ uint8_t g_n8[NNEG * D_DIM];        // e4m3
__device__ float g_pos[B_ANCH * P_POS];
__device__ float g_part[NGRP * B_ANCH];       // transposed: [gp][anchor]
__device__ float g_bsum[16];

// ================= helpers =================
__device__ __forceinline__ uint32_t smem_u32(const void* p) {
    uint32_t a;
    asm("{ .reg .u64 t; cvta.to.shared.u64 t, %1; cvt.u32.u64 %0, t; }" : "=r"(a) : "l"(p));
    return a;
}
__device__ __forceinline__ void cp_async16(uint32_t dst, const void* src) {
    asm volatile("cp.async.cg.shared.global [%0], [%1], 16;" :: "r"(dst), "l"(src) : "memory");
}
#define CP_COMMIT() asm volatile("cp.async.commit_group;" ::: "memory")
#define CP_WAIT(n)  asm volatile("cp.async.wait_group %0;" :: "n"(n) : "memory")

__device__ __forceinline__ float ex2(float x) {
    float r;
    asm("ex2.approx.f32 %0, %1;" : "=f"(r) : "f"(x));
    return r;
}

__device__ __forceinline__ uint32_t pack_e4m3_4(float x, float y, float z, float w) {
    uint16_t lo, hi;
    asm("cvt.rn.satfinite.e4m3x2.f32 %0, %1, %2;" : "=h"(lo) : "f"(y), "f"(x));
    asm("cvt.rn.satfinite.e4m3x2.f32 %0, %1, %2;" : "=h"(hi) : "f"(w), "f"(z));
    return (uint32_t)lo | ((uint32_t)hi << 16);
}

// fp8 mma with f16 accumulators
__device__ __forceinline__ void mma_fp8_h(uint32_t* c, const uint32_t* a,
                                          uint32_t b0, uint32_t b1) {
    asm volatile(
        "mma.sync.aligned.m16n8k32.row.col.f16.e4m3.e4m3.f16 "
        "{%0,%1}, {%2,%3,%4,%5}, {%6,%7}, {%0,%1};\n"
        : "+r"(c[0]), "+r"(c[1])
        : "r"(a[0]), "r"(a[1]), "r"(a[2]), "r"(a[3]), "r"(b0), "r"(b1));
}

// ldmatrix x4: loads B fragments for two consecutive j (n-row groups)
__device__ __forceinline__ void ldsm_x4(uint32_t& r0, uint32_t& r1,
                                        uint32_t& r2, uint32_t& r3, uint32_t a) {
    asm volatile("ldmatrix.sync.aligned.m8n8.x4.shared.b16 {%0,%1,%2,%3}, [%4];"
                 : "=r"(r0), "=r"(r1), "=r"(r2), "=r"(r3) : "r"(a));
}

// ============================================================
// Kernel 1: L2-normalize anchors + negatives -> e4m3
// ============================================================
__global__ void normalize_kernel(const float* __restrict__ anch,
                                 const float* __restrict__ neg) {
    int warp = threadIdx.x >> 5, lane = threadIdx.x & 31;
    int row = blockIdx.x * 8 + warp;
    const float* src;
    uint8_t* dst;
    if (row < B_ANCH) {
        src = anch + (size_t)row * D_DIM;  dst = g_a8 + (size_t)row * D_DIM;
    } else {
        int r = row - B_ANCH;
        if (r >= NNEG) return;
        src = neg + (size_t)r * D_DIM;     dst = g_n8 + (size_t)r * D_DIM;
    }
    const float4* s4 = (const float4*)src;
    float4 v0 = s4[lane], v1 = s4[lane + 32];
    float ss = v0.x*v0.x + v0.y*v0.y + v0.z*v0.z + v0.w*v0.w
             + v1.x*v1.x + v1.y*v1.y + v1.z*v1.z + v1.w*v1.w;
    #pragma unroll
    for (int o = 16; o; o >>= 1) ss += __shfl_xor_sync(0xFFFFFFFFu, ss, o);
    float inv = 1.0f / fmaxf(sqrtf(ss), EPSN);
    uint32_t* d32 = (uint32_t*)dst;
    d32[lane]      = pack_e4m3_4(v0.x*inv, v0.y*inv, v0.z*inv, v0.w*inv);
    d32[lane + 32] = pack_e4m3_4(v1.x*inv, v1.y*inv, v1.z*inv, v1.w*inv);
}

// ============================================================
// Kernel 2: pos_sim in fp32 (warp per pair) — exact
// ============================================================
__global__ void pos_kernel(const float* __restrict__ anch,
                           const float* __restrict__ pos) {
    int warp = threadIdx.x >> 5, lane = threadIdx.x & 31;
    int id = blockIdx.x * 8 + warp;
    if (id >= B_ANCH * P_POS) return;
    int b = id >> 2;
    const float4* a4 = (const float4*)(anch + (size_t)b * D_DIM);
    const float4* p4 = (const float4*)(pos  + (size_t)id * D_DIM);
    float4 a0 = a4[lane], a1 = a4[lane + 32];
    float4 p0 = p4[lane], p1 = p4[lane + 32];
    float dot = a0.x*p0.x + a0.y*p0.y + a0.z*p0.z + a0.w*p0.w
              + a1.x*p1.x + a1.y*p1.y + a1.z*p1.z + a1.w*p1.w;
    float asq = a0.x*a0.x + a0.y*a0.y + a0.z*a0.z + a0.w*a0.w
              + a1.x*a1.x + a1.y*a1.y + a1.z*a1.z + a1.w*a1.w;
    float psq = p0.x*p0.x + p0.y*p0.y + p0.z*p0.z + p0.w*p0.w
              + p1.x*p1.x + p1.y*p1.y + p1.z*p1.z + p1.w*p1.w;
    #pragma unroll
    for (int o = 16; o; o >>= 1) {
        dot += __shfl_xor_sync(0xFFFFFFFFu, dot, o);
        asq += __shfl_xor_sync(0xFFFFFFFFu, asq, o);
        psq += __shfl_xor_sync(0xFFFFFFFFu, psq, o);
    }
    if (lane == 0) {
        float denom = fmaxf(sqrtf(asq), EPSN) * fmaxf(sqrtf(psq), EPSN);
        g_pos[id] = dot / denom * INV_T;
    }
}

// ============================================================
// Kernel 3: fp8 mma.sync (f16 acc) GEMM + fused sum(exp(logit-20))
// B fragments via ldmatrix.x4; A register-resident; 3-stage cp.async.
// ============================================================
extern __shared__ uint8_t smem_raw[];

__global__ void __launch_bounds__(256, 2) gemm_lse_kernel() {
    uint8_t* sA = smem_raw;
    uint32_t sA_u = smem_u32(smem_raw);
    int tid = threadIdx.x;
    int w = tid >> 5, lane = tid & 31, g = lane >> 2, q = lane & 3;
    int m  = blockIdx.x & 15;
    int gp = blockIdx.x >> 4;
    int m0 = m * MT;
    int tstart = gp * 28 + min(gp, 8);      // 512 = 8*29 + 10*28
    int tcnt   = 28 + (gp < 8 ? 1 : 0);

    // per-lane ldmatrix base offset within a B buffer:
    // row = ((lane>>4)&1)*8 + (lane&7), col = ((lane>>3)&1)*16
    uint32_t ldsm_off = (uint32_t)((((lane >> 4) & 1) * 8 + (lane & 7)) * STR
                                   + ((lane >> 3) & 1) * 16);

    // ---- issue A tile load (32KB) ----
    {
        const uint8_t* gA = g_a8 + (size_t)m0 * D_DIM;
        #pragma unroll
        for (int i = 0; i < 8; i++) {
            int c = tid + i * 256;
            int r = c >> 4, c16 = c & 15;
            cp_async16(sA_u + r * STR + c16 * 16, gA + (size_t)r * 256 + c16 * 16);
        }
    }
    CP_COMMIT();

    // ---- preload B tiles 0,1 ----
    #pragma unroll
    for (int pb = 0; pb < 2; pb++) {
        const uint8_t* gB = g_n8 + (size_t)(tstart + pb) * NB * D_DIM;
        uint32_t sB_u = sA_u + A_BYTES + pb * B_BYTES;
        #pragma unroll
        for (int i = 0; i < 4; i++) {
            int c = tid + i * 256;
            int r = c >> 4, c16 = c & 15;
            cp_async16(sB_u + r * STR + c16 * 16, gB + (size_t)r * 256 + c16 * 16);
        }
        CP_COMMIT();
    }

    // ---- A fragments -> registers ----
    CP_WAIT(2);
    __syncthreads();
    uint32_t areg[32];
    {
        const uint8_t* r0 = sA + (size_t)(w * 16 + g) * STR;
        const uint8_t* r1 = r0 + 8 * STR;
        #pragma unroll
        for (int ks = 0; ks < 8; ks++) {
            int k0 = ks * 32;
            areg[4*ks+0] = *(const uint32_t*)(r0 + k0 + 4*q);
            areg[4*ks+1] = *(const uint32_t*)(r1 + k0 + 4*q);
            areg[4*ks+2] = *(const uint32_t*)(r0 + k0 + 16 + 4*q);
            areg[4*ks+3] = *(const uint32_t*)(r1 + k0 + 16 + 4*q);
        }
    }

    float rs0 = 0.0f, rs1 = 0.0f;

    for (int t = 0; t < tcnt; t++) {
        if (t < tcnt - 1) CP_WAIT(1); else CP_WAIT(0);
        __syncthreads();

        // prefetch tile t+2 into buffer (t+2)%3
        if (t + 2 < tcnt) {
            const uint8_t* gB = g_n8 + (size_t)(tstart + t + 2) * NB * D_DIM;
            uint32_t sB_u = sA_u + A_BYTES + ((t + 2) % 3) * B_BYTES;
            #pragma unroll
            for (int i = 0; i < 4; i++) {
                int c = tid + i * 256;
                int r = c >> 4, c16 = c & 15;
                cp_async16(sB_u + r * STR + c16 * 16, gB + (size_t)r * 256 + c16 * 16);
            }
            CP_COMMIT();
        }

        uint32_t sB_base = sA_u + A_BYTES + (t % 3) * B_BYTES + ldsm_off;
        uint32_t acc[8][2];
        #pragma unroll
        for (int j = 0; j < 8; j++) { acc[j][0] = 0u; acc[j][1] = 0u; }

        #pragma unroll
        for (int ks = 0; ks < 8; ks++) {
            uint32_t kb = sB_base + ks * 32;
            #pragma unroll
            for (int jj = 0; jj < 4; jj++) {
                uint32_t b00, b01, b10, b11;
                ldsm_x4(b00, b01, b10, b11, kb + jj * (16 * STR));
                mma_fp8_h(acc[2*jj],     areg + 4*ks, b00, b01);
                mma_fp8_h(acc[2*jj + 1], areg + 4*ks, b10, b11);
            }
        }

        // epilogue: accumulate exp2(dot*20*log2e - 20*log2e)
        #pragma unroll
        for (int j = 0; j < 8; j++) {
            float2 f0 = __half22float2(*(__half2*)&acc[j][0]);
            float2 f1 = __half22float2(*(__half2*)&acc[j][1]);
            rs0 += ex2(fmaf(f0.x, K2E, -K2E)) + ex2(fmaf(f0.y, K2E, -K2E));
            rs1 += ex2(fmaf(f1.x, K2E, -K2E)) + ex2(fmaf(f1.y, K2E, -K2E));
        }
    }

    // reduce across the quad (cols), write per-row partials (transposed)
    rs0 += __shfl_xor_sync(0xFFFFFFFFu, rs0, 1);
    rs0 += __shfl_xor_sync(0xFFFFFFFFu, rs0, 2);
    rs1 += __shfl_xor_sync(0xFFFFFFFFu, rs1, 1);
    rs1 += __shfl_xor_sync(0xFFFFFFFFu, rs1, 2);
    if (q == 0) {
        int row = m0 + w * 16 + g;
        g_part[(size_t)gp * B_ANCH + row]     = rs0;
        g_part[(size_t)gp * B_ANCH + row + 8] = rs1;
    }
}

// ============================================================
// Kernel 4a: per-anchor loss + block partial sums (grid 16 x 128)
// ============================================================
__global__ void finalize_a_kernel(const int* __restrict__ counts) {
    __shared__ float red[128];
    int tid = threadIdx.x;
    int b = blockIdx.x * 128 + tid;

    float s = 0.0f;
    #pragma unroll
    for (int c = 0; c < NGRP; c++) s += g_part[(size_t)c * B_ANCH + b];
    float lse = 20.0f + logf(s);
    int cnt = counts[b];
    float ps[4];
    #pragma unroll
    for (int j = 0; j < 4; j++) ps[j] = g_pos[b * 4 + j];

    float local = 0.0f;
    #pragma unroll
    for (int j = 0; j < 4; j++) {
        if (j < cnt) {
            float mx = fmaxf(ps[j], lse);
            local += mx + log1pf(expf(fminf(ps[j], lse) - mx)) - ps[j];
        }
    }
    float mx = fmaxf(fmaxf(ps[0], ps[1]), fmaxf(ps[2], ps[3]));
    float e0 = expf(ps[0] - mx), e1 = expf(ps[1] - mx);
    float e2 = expf(ps[2] - mx), e3 = expf(ps[3] - mx);
    float wps = (e0*ps[0] + e1*ps[1] + e2*ps[2] + e3*ps[3]) / (e0 + e1 + e2 + e3);
    if (cnt > 1) {
        float m2 = fmaxf(wps, lse);
        local += ALPHA * (m2 + log1pf(expf(fminf(wps, lse) - m2)) - wps);
    }

    red[tid] = local;
    __syncthreads();
    #pragma unroll
    for (int o = 64; o; o >>= 1) {
        if (tid < o) red[tid] += red[tid + o];
        __syncthreads();
    }
    if (tid == 0) g_bsum[blockIdx.x] = red[0];
}

__global__ void finalize_b_kernel(float* __restrict__ out) {
    if (threadIdx.x == 0) {
        float t = 0.0f;
        #pragma unroll
        for (int i = 0; i < 16; i++) t += g_bsum[i];
        out[0] = t / (float)B_ANCH;
    }
}

// ============================================================
extern "C" void kernel_launch(void* const* d_in, const int* in_sizes, int n_in,
                              void* d_out, int out_size) {
    const float* anch   = (const float*)d_in[0];
    const float* pos    = (const float*)d_in[1];
    const float* neg    = (const float*)d_in[2];
    const int*   counts = (const int*)d_in[3];
    float* out = (float*)d_out;

    cudaFuncSetAttribute(gemm_lse_kernel,
                         cudaFuncAttributeMaxDynamicSharedMemorySize, SMEM_TOTAL);

    normalize_kernel<<<(B_ANCH + NNEG) / 8, 256>>>(anch, neg);
    pos_kernel<<<(B_ANCH * P_POS) / 8, 256>>>(anch, pos);
    gemm_lse_kernel<<<MBLKS * NGRP, 256, SMEM_TOTAL>>>();
    finalize_a_kernel<<<16, 128>>>(counts);
    finalize_b_kernel<<<1, 32>>>(out);
}

// round 9
// speedup vs baseline: 2.3535x; 1.0129x over previous
#include <cuda_runtime.h>
#include <cuda_fp16.h>
#include <cstdint>

#define B_ANCH 2048
#define P_POS  4
#define D_DIM  256            // K
#define NNEG   32768
#define ALPHA  0.1f
#define EPSN   1e-12f
#define INV_T  20.0f          // 1/temperature
#define K2E    28.85390081777927f   // 20 * log2(e)
#define SHIFT2 8.0f                 // log2-domain shift: sum exp2(logit2 - 8)

#define MT     128            // anchors per CTA
#define NB     64             // negatives per subtile
#define MBLKS  (B_ANCH / MT)  // 16
#define NGRP   18             // N-groups -> grid 16*18 = 288 CTAs
#define STR    272            // smem row stride bytes (256 data + 16 pad)

#define A_BYTES (MT * STR)          // 34816
#define B_BYTES (NB * STR)          // 17408
#define SMEM_TOTAL (A_BYTES + 3 * B_BYTES)   // 87040

// ---- scratch ----
__device__ uint8_t g_a8[B_ANCH * D_DIM];      // e4m3
__device__ uint8_t g_n8[NNEG * D_DIM];        // e4m3
__device__ float g_pos[B_ANCH * P_POS];
__device__ float g_part[NGRP * B_ANCH];       // transposed: [gp][anchor]

// ================= helpers =================
__device__ __forceinline__ uint32_t smem_u32(const void* p) {
    uint32_t a;
    asm("{ .reg .u64 t; cvta.to.shared.u64 t, %1; cvt.u32.u64 %0, t; }" : "=r"(a) : "l"(p));
    return a;
}
__device__ __forceinline__ void cp_async16(uint32_t dst, const void* src) {
    asm volatile("cp.async.cg.shared.global [%0], [%1], 16;" :: "r"(dst), "l"(src) : "memory");
}
#define CP_COMMIT() asm volatile("cp.async.commit_group;" ::: "memory")
#define CP_WAIT(n)  asm volatile("cp.async.wait_group %0;" :: "n"(n) : "memory")

__device__ __forceinline__ uint32_t pack_e4m3_4(float x, float y, float z, float w) {
    uint16_t lo, hi;
    asm("cvt.rn.satfinite.e4m3x2.f32 %0, %1, %2;" : "=h"(lo) : "f"(y), "f"(x));
    asm("cvt.rn.satfinite.e4m3x2.f32 %0, %1, %2;" : "=h"(hi) : "f"(w), "f"(z));
    return (uint32_t)lo | ((uint32_t)hi << 16);
}

// fp8 mma with f16 accumulators
__device__ __forceinline__ void mma_fp8_h(uint32_t* c, const uint32_t* a,
                                          uint32_t b0, uint32_t b1) {
    asm volatile(
        "mma.sync.aligned.m16n8k32.row.col.f16.e4m3.e4m3.f16 "
        "{%0,%1}, {%2,%3,%4,%5}, {%6,%7}, {%0,%1};\n"
        : "+r"(c[0]), "+r"(c[1])
        : "r"(a[0]), "r"(a[1]), "r"(a[2]), "r"(a[3]), "r"(b0), "r"(b1));
}

// ldmatrix x4
__device__ __forceinline__ void ldsm_x4(uint32_t& r0, uint32_t& r1,
                                        uint32_t& r2, uint32_t& r3, uint32_t a) {
    asm volatile("ldmatrix.sync.aligned.m8n8.x4.shared.b16 {%0,%1,%2,%3}, [%4];"
                 : "=r"(r0), "=r"(r1), "=r"(r2), "=r"(r3) : "r"(a));
}

// ============================================================
// Kernel 1: fused prep — normalize (a,n -> e4m3) and pos_sim
// one warp per task; tasks: [0, B+N) normalize, [B+N, B+N+B*P) pos
// ============================================================
__global__ void prep_kernel(const float* __restrict__ anch,
                            const float* __restrict__ pos,
                            const float* __restrict__ neg) {
    int warp = threadIdx.x >> 5, lane = threadIdx.x & 31;
    int id = blockIdx.x * 8 + warp;

    if (id < B_ANCH + NNEG) {
        // ---- normalize task ----
        const float* src;
        uint8_t* dst;
        if (id < B_ANCH) {
            src = anch + (size_t)id * D_DIM;  dst = g_a8 + (size_t)id * D_DIM;
        } else {
            int r = id - B_ANCH;
            src = neg + (size_t)r * D_DIM;    dst = g_n8 + (size_t)r * D_DIM;
        }
        const float4* s4 = (const float4*)src;
        float4 v0 = s4[lane], v1 = s4[lane + 32];
        float ss = v0.x*v0.x + v0.y*v0.y + v0.z*v0.z + v0.w*v0.w
                 + v1.x*v1.x + v1.y*v1.y + v1.z*v1.z + v1.w*v1.w;
        #pragma unroll
        for (int o = 16; o; o >>= 1) ss += __shfl_xor_sync(0xFFFFFFFFu, ss, o);
        float inv = 1.0f / fmaxf(sqrtf(ss), EPSN);
        uint32_t* d32 = (uint32_t*)dst;
        d32[lane]      = pack_e4m3_4(v0.x*inv, v0.y*inv, v0.z*inv, v0.w*inv);
        d32[lane + 32] = pack_e4m3_4(v1.x*inv, v1.y*inv, v1.z*inv, v1.w*inv);
    } else {
        // ---- pos_sim task (exact fp32) ----
        int pid = id - (B_ANCH + NNEG);
        if (pid >= B_ANCH * P_POS) return;
        int b = pid >> 2;
        const float4* a4 = (const float4*)(anch + (size_t)b * D_DIM);
        const float4* p4 = (const float4*)(pos  + (size_t)pid * D_DIM);
        float4 a0 = a4[lane], a1 = a4[lane + 32];
        float4 p0 = p4[lane], p1 = p4[lane + 32];
        float dot = a0.x*p0.x + a0.y*p0.y + a0.z*p0.z + a0.w*p0.w
                  + a1.x*p1.x + a1.y*p1.y + a1.z*p1.z + a1.w*p1.w;
        float asq = a0.x*a0.x + a0.y*a0.y + a0.z*a0.z + a0.w*a0.w
                  + a1.x*a1.x + a1.y*a1.y + a1.z*a1.z + a1.w*a1.w;
        float psq = p0.x*p0.x + p0.y*p0.y + p0.z*p0.z + p0.w*p0.w
                  + p1.x*p1.x + p1.y*p1.y + p1.z*p1.z + p1.w*p1.w;
        #pragma unroll
        for (int o = 16; o; o >>= 1) {
            dot += __shfl_xor_sync(0xFFFFFFFFu, dot, o);
            asq += __shfl_xor_sync(0xFFFFFFFFu, asq, o);
            psq += __shfl_xor_sync(0xFFFFFFFFu, psq, o);
        }
        if (lane == 0) {
            float denom = fmaxf(sqrtf(asq), EPSN) * fmaxf(sqrtf(psq), EPSN);
            g_pos[pid] = dot / denom * INV_T;
        }
    }
}

// ============================================================
// Kernel 2: fp8 mma.sync (f16 acc) GEMM + fused sum(exp2(l2-8))
// half2 epilogue: HFMA2 -> ex2.f16x2 -> HADD2
// ============================================================
extern __shared__ uint8_t smem_raw[];

__global__ void __launch_bounds__(256, 2) gemm_lse_kernel() {
    uint8_t* sA = smem_raw;
    uint32_t sA_u = smem_u32(smem_raw);
    int tid = threadIdx.x;
    int w = tid >> 5, lane = tid & 31, g = lane >> 2, q = lane & 3;
    int m  = blockIdx.x & 15;
    int gp = blockIdx.x >> 4;
    int m0 = m * MT;
    int tstart = gp * 28 + min(gp, 8);      // 512 = 8*29 + 10*28
    int tcnt   = 28 + (gp < 8 ? 1 : 0);

    const __half2 k2h = __float2half2_rn(K2E);
    const __half2 c8h = __float2half2_rn(-SHIFT2);

    uint32_t ldsm_off = (uint32_t)((((lane >> 4) & 1) * 8 + (lane & 7)) * STR
                                   + ((lane >> 3) & 1) * 16);

    // ---- issue A tile load (32KB) ----
    {
        const uint8_t* gA = g_a8 + (size_t)m0 * D_DIM;
        #pragma unroll
        for (int i = 0; i < 8; i++) {
            int c = tid + i * 256;
            int r = c >> 4, c16 = c & 15;
            cp_async16(sA_u + r * STR + c16 * 16, gA + (size_t)r * 256 + c16 * 16);
        }
    }
    CP_COMMIT();

    // ---- preload B tiles 0,1 ----
    #pragma unroll
    for (int pb = 0; pb < 2; pb++) {
        const uint8_t* gB = g_n8 + (size_t)(tstart + pb) * NB * D_DIM;
        uint32_t sB_u = sA_u + A_BYTES + pb * B_BYTES;
        #pragma unroll
        for (int i = 0; i < 4; i++) {
            int c = tid + i * 256;
            int r = c >> 4, c16 = c & 15;
            cp_async16(sB_u + r * STR + c16 * 16, gB + (size_t)r * 256 + c16 * 16);
        }
        CP_COMMIT();
    }

    // ---- A fragments -> registers ----
    CP_WAIT(2);
    __syncthreads();
    uint32_t areg[32];
    {
        const uint8_t* r0 = sA + (size_t)(w * 16 + g) * STR;
        const uint8_t* r1 = r0 + 8 * STR;
        #pragma unroll
        for (int ks = 0; ks < 8; ks++) {
            int k0 = ks * 32;
            areg[4*ks+0] = *(const uint32_t*)(r0 + k0 + 4*q);
            areg[4*ks+1] = *(const uint32_t*)(r1 + k0 + 4*q);
            areg[4*ks+2] = *(const uint32_t*)(r0 + k0 + 16 + 4*q);
            areg[4*ks+3] = *(const uint32_t*)(r1 + k0 + 16 + 4*q);
        }
    }

    float rs0 = 0.0f, rs1 = 0.0f;

    for (int t = 0; t < tcnt; t++) {
        if (t < tcnt - 1) CP_WAIT(1); else CP_WAIT(0);
        __syncthreads();

        // prefetch tile t+2 into buffer (t+2)%3
        if (t + 2 < tcnt) {
            const uint8_t* gB = g_n8 + (size_t)(tstart + t + 2) * NB * D_DIM;
            uint32_t sB_u = sA_u + A_BYTES + ((t + 2) % 3) * B_BYTES;
            #pragma unroll
            for (int i = 0; i < 4; i++) {
                int c = tid + i * 256;
                int r = c >> 4, c16 = c & 15;
                cp_async16(sB_u + r * STR + c16 * 16, gB + (size_t)r * 256 + c16 * 16);
            }
            CP_COMMIT();
        }

        uint32_t sB_base = sA_u + A_BYTES + (t % 3) * B_BYTES + ldsm_off;
        uint32_t acc[8][2];
        #pragma unroll
        for (int j = 0; j < 8; j++) { acc[j][0] = 0u; acc[j][1] = 0u; }

        #pragma unroll
        for (int ks = 0; ks < 8; ks++) {
            uint32_t kb = sB_base + ks * 32;
            #pragma unroll
            for (int jj = 0; jj < 4; jj++) {
                uint32_t b00, b01, b10, b11;
                ldsm_x4(b00, b01, b10, b11, kb + jj * (16 * STR));
                mma_fp8_h(acc[2*jj],     areg + 4*ks, b00, b01);
                mma_fp8_h(acc[2*jj + 1], areg + 4*ks, b10, b11);
            }
        }

        // half2 epilogue: hs += exp2(acc*K2E - 8)
        __half2 hs0 = __float2half2_rn(0.0f);
        __half2 hs1 = __float2half2_rn(0.0f);
        #pragma unroll
        for (int j = 0; j < 8; j++) {
            __half2 a0 = *(__half2*)&acc[j][0];
            __half2 a1 = *(__half2*)&acc[j][1];
            hs0 = __hadd2(hs0, h2exp2(__hfma2(a0, k2h, c8h)));
            hs1 = __hadd2(hs1, h2exp2(__hfma2(a1, k2h, c8h)));
        }
        float2 f0 = __half22float2(hs0);
        float2 f1 = __half22float2(hs1);
        rs0 += f0.x + f0.y;
        rs1 += f1.x + f1.y;
    }

    // reduce across the quad (cols), write per-row partials (transposed)
    rs0 += __shfl_xor_sync(0xFFFFFFFFu, rs0, 1);
    rs0 += __shfl_xor_sync(0xFFFFFFFFu, rs0, 2);
    rs1 += __shfl_xor_sync(0xFFFFFFFFu, rs1, 1);
    rs1 += __shfl_xor_sync(0xFFFFFFFFu, rs1, 2);
    if (q == 0) {
        int row = m0 + w * 16 + g;
        g_part[(size_t)gp * B_ANCH + row]     = rs0;
        g_part[(size_t)gp * B_ANCH + row + 8] = rs1;
    }
}

// ============================================================
// Kernel 3: finalize — single block, 1024 threads, 2 anchors each
// note: partials are sums of exp2(logit2 - 8) = exp(logit)*2^-8
//       -> lse = 8*ln2 + log(s)
// ============================================================
__global__ void finalize_kernel(const int* __restrict__ counts,
                                float* __restrict__ out) {
    __shared__ float red[1024];
    int tid = threadIdx.x;
    float local = 0.0f;

    #pragma unroll
    for (int bb = 0; bb < 2; bb++) {
        int b = tid + bb * 1024;
        float s = 0.0f;
        #pragma unroll
        for (int c = 0; c < NGRP; c++) s += g_part[(size_t)c * B_ANCH + b];
        float lse = 5.545177444479562f + logf(s);    // 8*ln2 + log(s)
        int cnt = counts[b];
        float ps[4];
        #pragma unroll
        for (int j = 0; j < 4; j++) ps[j] = g_pos[b * 4 + j];

        #pragma unroll
        for (int j = 0; j < 4; j++) {
            if (j < cnt) {
                float mx = fmaxf(ps[j], lse);
                local += mx + log1pf(expf(fminf(ps[j], lse) - mx)) - ps[j];
            }
        }
        float mx = fmaxf(fmaxf(ps[0], ps[1]), fmaxf(ps[2], ps[3]));
        float e0 = expf(ps[0] - mx), e1 = expf(ps[1] - mx);
        float e2 = expf(ps[2] - mx), e3 = expf(ps[3] - mx);
        float wps = (e0*ps[0] + e1*ps[1] + e2*ps[2] + e3*ps[3]) / (e0 + e1 + e2 + e3);
        if (cnt > 1) {
            float m2 = fmaxf(wps, lse);
            local += ALPHA * (m2 + log1pf(expf(fminf(wps, lse) - m2)) - wps);
        }
    }

    red[tid] = local;
    __syncthreads();
    #pragma unroll
    for (int o = 512; o; o >>= 1) {
        if (tid < o) red[tid] += red[tid + o];
        __syncthreads();
    }
    if (tid == 0) out[0] = red[0] / (float)B_ANCH;
}

// ============================================================
extern "C" void kernel_launch(void* const* d_in, const int* in_sizes, int n_in,
                              void* d_out, int out_size) {
    const float* anch   = (const float*)d_in[0];
    const float* pos    = (const float*)d_in[1];
    const float* neg    = (const float*)d_in[2];
    const int*   counts = (const int*)d_in[3];
    float* out = (float*)d_out;

    cudaFuncSetAttribute(gemm_lse_kernel,
                         cudaFuncAttributeMaxDynamicSharedMemorySize, SMEM_TOTAL);

    prep_kernel<<<(B_ANCH + NNEG + B_ANCH * P_POS) / 8, 256>>>(anch, pos, neg);
    gemm_lse_kernel<<<MBLKS * NGRP, 256, SMEM_TOTAL>>>();
    finalize_kernel<<<1, 1024>>>(counts, out);
}